// round 6
// baseline (speedup 1.0000x reference)
#include <cuda_runtime.h>
#include <cuda_bf16.h>
#include <cstdint>

#define C_DIM 512
#define K_DIM 150
#define K_PAD 160
#define KC    32
#define SPLITS 37

// ---------------- device scratch ----------------
__device__ float g_acc[C_DIM * K_PAD];   // acc[c][k]
__device__ float g_S[K_PAD];

// ---------------- PTX helpers (arch-agnostic sm_80-level only) ----------------
__device__ __forceinline__ uint32_t smem_u32(const void* p) {
    uint32_t a;
    asm("{ .reg .u64 t; cvta.to.shared.u64 t, %1; cvt.u32.u64 %0, t; }" : "=r"(a) : "l"(p));
    return a;
}
__device__ __forceinline__ void cp16(uint32_t dst, const void* src) {
    asm volatile("cp.async.ca.shared.global [%0], [%1], 16;" :: "r"(dst), "l"(src) : "memory");
}
#define CP_COMMIT() asm volatile("cp.async.commit_group;" ::: "memory")
#define CP_WAIT1()  asm volatile("cp.async.wait_group 1;" ::: "memory")

#define LDSM_X4(r0, r1, r2, r3, addr) \
    asm volatile("ldmatrix.sync.aligned.m8n8.x4.shared.b16 {%0,%1,%2,%3}, [%4];" \
        : "=r"(r0), "=r"(r1), "=r"(r2), "=r"(r3) : "r"(addr))

#define MMA_BF16(d, a0, a1, a2, a3, b0, b1) \
    asm volatile("mma.sync.aligned.m16n8k16.row.col.f32.bf16.bf16.f32 " \
        "{%0,%1,%2,%3}, {%4,%5,%6,%7}, {%8,%9}, {%0,%1,%2,%3};" \
        : "+f"((d)[0]), "+f"((d)[1]), "+f"((d)[2]), "+f"((d)[3]) \
        : "r"(a0), "r"(a1), "r"(a2), "r"(a3), "r"(b0), "r"(b1))

__device__ __forceinline__ void cvt_hl(float2 v, uint32_t& h, uint32_t& l) {
    __nv_bfloat162 hb = __float22bfloat162_rn(v);
    __nv_bfloat162 lb = __float22bfloat162_rn(
        make_float2(v.x - __bfloat162float(hb.x), v.y - __bfloat162float(hb.y)));
    h = *reinterpret_cast<uint32_t*>(&hb);
    l = *reinterpret_cast<uint32_t*>(&lb);
}

// ---------------- smem layout ----------------
#define L_STRIDE 144
#define L_STAGE  21632
#define B_BASE   (3 * L_STAGE)          // 64896
#define B_PAIR   25600
#define BL_OFF   12800
#define SMEM_TOT (B_BASE + 2 * B_PAIR)  // 116096

// ---------------- K0: zero accumulators ----------------
__global__ void zero_kernel() {
    int i = blockIdx.x * blockDim.x + threadIdx.x;
    if (i < C_DIM * K_PAD) g_acc[i] = 0.0f;
    if (i < K_PAD) g_S[i] = 0.0f;
}

__device__ __forceinline__ void issue_logits(uint32_t sb0, int s, const float* __restrict__ logits,
                                             size_t n0, int tid, int N) {
    #pragma unroll
    for (int i = 0; i < 5; i++) {
        int idx = tid + i * 256;                  // 150 rows x 8 units = 1200
        if (idx < 1200) {
            int r = idx >> 3, u = idx & 7;
            cp16(sb0 + (uint32_t)s * L_STAGE + r * L_STRIDE + u * 16,
                 (const void*)(logits + (size_t)r * N + n0 + u * 4));
        }
    }
}

// MMA block: consume B buffer at sb (hi at +0, lo at +BL_OFF) with frags Ah/Al
__device__ __forceinline__ void mma_block(uint32_t sb, uint32_t b_base,
                                          const uint32_t Ah[2][4], const uint32_t Al[2][4],
                                          float acc[20][4]) {
    #pragma unroll
    for (int k16 = 0; k16 < 2; k16++) {
        uint32_t ko = (uint32_t)k16 * 32;
        #pragma unroll
        for (int nfp = 0; nfp < 10; nfp++) {
            uint32_t bh0, bh1, bh2, bh3, bl0, bl1, bl2, bl3;
            uint32_t ba = sb + b_base + (uint32_t)nfp * 1280 + ko;
            LDSM_X4(bh0, bh1, bh2, bh3, ba);
            LDSM_X4(bl0, bl1, bl2, bl3, ba + BL_OFF);
            MMA_BF16(acc[2*nfp],   Ah[k16][0], Ah[k16][1], Ah[k16][2], Ah[k16][3], bh0, bh1);
            MMA_BF16(acc[2*nfp],   Ah[k16][0], Ah[k16][1], Ah[k16][2], Ah[k16][3], bl0, bl1);
            MMA_BF16(acc[2*nfp],   Al[k16][0], Al[k16][1], Al[k16][2], Al[k16][3], bh0, bh1);
            MMA_BF16(acc[2*nfp+1], Ah[k16][0], Ah[k16][1], Ah[k16][2], Ah[k16][3], bh2, bh3);
            MMA_BF16(acc[2*nfp+1], Ah[k16][0], Ah[k16][1], Ah[k16][2], Ah[k16][3], bl2, bl3);
            MMA_BF16(acc[2*nfp+1], Al[k16][0], Al[k16][1], Al[k16][2], Al[k16][3], bh2, bh3);
        }
    }
}

// ---------------- fused kernel: softmax-in-GEMM, shifted pipeline ----------------
__global__ __launch_bounds__(256, 1) void fused_kernel(const float* __restrict__ feats,
                                                       const float* __restrict__ logits, int N) {
    extern __shared__ char smem[];
    uint32_t sb0 = smem_u32(smem);
    int tid = threadIdx.x, lane = tid & 31, w = tid >> 5;
    int c0 = blockIdx.y * 128;
    int split = blockIdx.x;
    int cnt = (N / KC - 1 - split) / SPLITS + 1;

    // zero B pad rows (k=150..159) of both buffers, both arrays
    for (int i = tid; i < 800; i += 256) {
        int reg = i / 200, off = i % 200;
        *(uint32_t*)(smem + B_BASE + (reg >> 1) * B_PAIR + (reg & 1) * BL_OFF + 150 * 80 + off * 4) = 0u;
    }

    float acc[20][4];
    #pragma unroll
    for (int nf = 0; nf < 20; nf++)
        #pragma unroll
        for (int q = 0; q < 4; q++) acc[nf][q] = 0.0f;

    float S_part[19];
    #pragma unroll
    for (int i = 0; i < 19; i++) S_part[i] = 0.0f;

    const float* A0 = feats + (size_t)(c0 + w * 16 + (lane >> 2)) * N + (lane & 3) * 2;
    const float* A1 = A0 + (size_t)8 * N;
    int g = tid >> 3, t8 = tid & 7;

    float2 fb[8];
    {   // prologue: A chunk0 -> fb, logits stages 0,1 in flight
        size_t n = (size_t)split * KC;
        fb[0] = *(const float2*)(A0 + n);      fb[1] = *(const float2*)(A1 + n);
        fb[2] = *(const float2*)(A0 + n + 8);  fb[3] = *(const float2*)(A1 + n + 8);
        fb[4] = *(const float2*)(A0 + n + 16); fb[5] = *(const float2*)(A1 + n + 16);
        fb[6] = *(const float2*)(A0 + n + 24); fb[7] = *(const float2*)(A1 + n + 24);
        issue_logits(sb0, 0, logits, n, tid, N);
        CP_COMMIT();
        if (cnt > 1) issue_logits(sb0, 1, logits, n + (size_t)SPLITS * KC, tid, N);
        CP_COMMIT();
    }

    uint32_t b_base = (uint32_t)(((lane & 7) + ((lane >> 4) & 1) * 8) * 80 + ((lane >> 3) & 1) * 16);
    uint32_t Ah[2][4], Al[2][4];   // frags for chunk j (built in iter j, used in iter j+1)

    for (int j = 0; j < cnt; j++) {
        CP_WAIT1();                  // own stage-j copies complete (stage j+1 may pend)
        __syncthreads();             // all copies visible; B buffer handoff sealed

        // issue logits stage j+2 (into stage (j-1)%3, free after the sync)
        if (j + 2 < cnt)
            issue_logits(sb0, (j + 2) % 3, logits,
                         ((size_t)split + (size_t)(j + 2) * SPLITS) * KC, tid, N);
        CP_COMMIT();

        // hoist softmax loads: latency hides under the MMA block
        const char* Ls = smem + (j % 3) * L_STAGE;
        float vals[19];
        #pragma unroll
        for (int i = 0; i < 19; i++) {
            int k = t8 + 8 * i;
            vals[i] = (k < K_DIM) ? *(const float*)(Ls + k * L_STRIDE + g * 4) : -3.0e38f;
        }

        // MMA for PREVIOUS chunk (B[(j-1)%2], frags from iter j-1)
        if (j > 0)
            mma_block(sb0 + B_BASE + (uint32_t)((j - 1) & 1) * B_PAIR, b_base, Ah, Al, acc);

        // convert A chunk j -> frags (fb freed)
        #pragma unroll
        for (int k16 = 0; k16 < 2; k16++)
            #pragma unroll
            for (int q = 0; q < 4; q++)
                cvt_hl(fb[k16 * 4 + q], Ah[k16][q], Al[k16][q]);

        // prefetch A chunk j+1
        if (j + 1 < cnt) {
            size_t n = ((size_t)split + (size_t)(j + 1) * SPLITS) * KC;
            fb[0] = *(const float2*)(A0 + n);      fb[1] = *(const float2*)(A1 + n);
            fb[2] = *(const float2*)(A0 + n + 8);  fb[3] = *(const float2*)(A1 + n + 8);
            fb[4] = *(const float2*)(A0 + n + 16); fb[5] = *(const float2*)(A1 + n + 16);
            fb[6] = *(const float2*)(A0 + n + 24); fb[7] = *(const float2*)(A1 + n + 24);
        }

        // softmax compute chunk j -> B[j%2]
        {
            float m = -3.0e38f;
            #pragma unroll
            for (int i = 0; i < 19; i++) m = fmaxf(m, vals[i]);
            m = fmaxf(m, __shfl_xor_sync(0xffffffffu, m, 1));
            m = fmaxf(m, __shfl_xor_sync(0xffffffffu, m, 2));
            m = fmaxf(m, __shfl_xor_sync(0xffffffffu, m, 4));
            float z = 0.0f;
            #pragma unroll
            for (int i = 0; i < 19; i++) { vals[i] = __expf(vals[i] - m); z += vals[i]; }
            z += __shfl_xor_sync(0xffffffffu, z, 1);
            z += __shfl_xor_sync(0xffffffffu, z, 2);
            z += __shfl_xor_sync(0xffffffffu, z, 4);
            float invz = 1.0f / z;
            char* bh = smem + B_BASE + (j & 1) * B_PAIR;
            char* bl = bh + BL_OFF;
            #pragma unroll
            for (int i = 0; i < 19; i++) {
                int k = t8 + 8 * i;
                if (k < K_DIM) {
                    float p = vals[i] * invz;
                    S_part[i] += p;
                    __nv_bfloat16 h = __float2bfloat16(p);
                    __nv_bfloat16 l = __float2bfloat16(p - __bfloat162float(h));
                    *(uint16_t*)(bh + k * 80 + g * 2) = *(uint16_t*)&h;
                    *(uint16_t*)(bl + k * 80 + g * 2) = *(uint16_t*)&l;
                }
            }
        }
    }

    // tail: MMA for the last chunk
    __syncthreads();
    mma_block(sb0 + B_BASE + (uint32_t)((cnt - 1) & 1) * B_PAIR, b_base, Ah, Al, acc);

    // ---- epilogue ----
    int gr = lane >> 2, tg = lane & 3;
    int row = c0 + w * 16 + gr;
    #pragma unroll
    for (int nf = 0; nf < 20; nf++) {
        int col = nf * 8 + tg * 2;
        atomicAdd(&g_acc[row * K_PAD + col],           acc[nf][0]);
        atomicAdd(&g_acc[row * K_PAD + col + 1],       acc[nf][1]);
        atomicAdd(&g_acc[(row + 8) * K_PAD + col],     acc[nf][2]);
        atomicAdd(&g_acc[(row + 8) * K_PAD + col + 1], acc[nf][3]);
    }
    if (blockIdx.y == 0) {
        #pragma unroll
        for (int i = 0; i < 19; i++) {
            int k = t8 + 8 * i;
            if (k < K_DIM) atomicAdd(&g_S[k], S_part[i]);
        }
    }
}

// ---------------- finalize ----------------
__global__ void finalize_kernel(float* __restrict__ out) {
    int k = blockIdx.x, ci = threadIdx.x;
    out[k * C_DIM + ci] = g_acc[ci * K_PAD + k] / fmaxf(g_S[k], 1e-6f);
}

// ---------------- launch ----------------
extern "C" void kernel_launch(void* const* d_in, const int* in_sizes, int n_in,
                              void* d_out, int out_size) {
    const float* feats  = (const float*)d_in[0];   // (512, H, W)
    const float* logits = (const float*)d_in[1];   // (150, H, W)
    float* out = (float*)d_out;                    // (150, 512)
    int N = in_sizes[0] / C_DIM;                   // 262144

    cudaFuncSetAttribute(fused_kernel, cudaFuncAttributeMaxDynamicSharedMemorySize, SMEM_TOT);

    zero_kernel<<<(C_DIM * K_PAD + 255) / 256, 256>>>();
    fused_kernel<<<dim3(SPLITS, C_DIM / 128), 256, SMEM_TOT>>>(feats, logits, N);
    finalize_kernel<<<K_DIM, C_DIM>>>(out);
}